// round 5
// baseline (speedup 1.0000x reference)
#include <cuda_runtime.h>
#include <math.h>

// FFT long convolution: y = (x (*) h)[0:L] / (2L), per row.
// n = 16384 complex FFT per row, z = x + i*h packing. One CTA per row.
// Fused register-staged radix-16 passes (2x radix-4 in registers).
// Pad: buf index i lives at i + (i>>4)  -> all buf passes bank-conflict-free.

#define NF 16384
#define NH 8192
#define NT 512
#define NFP (NF + (NF >> 4))                      // 17408 float2
#define SMEM_BYTES ((NFP + NH) * (int)sizeof(float2))  // 139264 + 65536 = 204800 B

__device__ __forceinline__ float2& B(float2* buf, int i) {
    return buf[i + (i >> 4)];
}

__device__ __forceinline__ float2 cmul(float2 a, float2 b) {
    return make_float2(a.x * b.x - a.y * b.y, a.x * b.y + a.y * b.x);
}

// twiddle: exp(-2*pi*i*e/NF); table holds e in [0, NH)
__device__ __forceinline__ float2 gtw(const float2* __restrict__ tw, int e) {
    float2 t = tw[e & (NH - 1)];
    if (e & NH) { t.x = -t.x; t.y = -t.y; }
    return t;
}
__device__ __forceinline__ float2 gtwc(const float2* __restrict__ tw, int e) {
    float2 t = gtw(tw, e);
    t.y = -t.y;
    return t;
}

// base-4 digit reversal of 7 digits (14 bits)
__device__ __forceinline__ int drev14(int p) {
    unsigned r = __brev((unsigned)p) >> 18;
    return (int)(((r & 0x1555u) << 1) | ((r >> 1) & 0x1555u));
}

// ---- DIF radix-4 butterfly on (a0..a3); outputs to same slots, legs 1..3 twiddled
#define DIF_BFLY(a0, a1, a2, a3, w1, w2, w3)                                  \
    {                                                                          \
        float2 t0 = make_float2(a0.x + a2.x, a0.y + a2.y);                     \
        float2 t1 = make_float2(a0.x - a2.x, a0.y - a2.y);                     \
        float2 t2 = make_float2(a1.x + a3.x, a1.y + a3.y);                     \
        float2 t3 = make_float2(a1.x - a3.x, a1.y - a3.y);                     \
        float2 A0 = make_float2(t0.x + t2.x, t0.y + t2.y);                     \
        float2 A2 = make_float2(t0.x - t2.x, t0.y - t2.y);                     \
        float2 A1 = make_float2(t1.x + t3.y, t1.y - t3.x);  /* t1 - i t3 */    \
        float2 A3 = make_float2(t1.x - t3.y, t1.y + t3.x);  /* t1 + i t3 */    \
        a0 = A0; a1 = cmul(A1, w1); a2 = cmul(A2, w2); a3 = cmul(A3, w3);      \
    }

// ---- DIT radix-4 butterfly: legs 1..3 pre-twiddled, outputs to same slots
#define DIT_BFLY(a0, a1, a2, a3, w1, w2, w3)                                  \
    {                                                                          \
        float2 b0 = a0;                                                        \
        float2 b1 = cmul(a1, w1);                                              \
        float2 b2 = cmul(a2, w2);                                              \
        float2 b3 = cmul(a3, w3);                                              \
        float2 s0 = make_float2(b0.x + b2.x, b0.y + b2.y);                     \
        float2 s1 = make_float2(b0.x - b2.x, b0.y - b2.y);                     \
        float2 s2 = make_float2(b1.x + b3.x, b1.y + b3.y);                     \
        float2 s3 = make_float2(b1.x - b3.x, b1.y - b3.y);                     \
        a0 = make_float2(s0.x + s2.x, s0.y + s2.y);                            \
        a1 = make_float2(s1.x - s3.y, s1.y + s3.x);  /* s1 + i s3 */           \
        a2 = make_float2(s0.x - s2.x, s0.y - s2.y);                            \
        a3 = make_float2(s1.x + s3.y, s1.y - s3.x);  /* s1 - i s3 */           \
    }

// Fused forward pass: DIF stages q_A = 4Q then q_B = Q, register-staged.
template <int Q>
__device__ __forceinline__ void fwd_pass(float2* buf, const float2* tw, int tid) {
    const int stepA = NF / (16 * Q);
    const int stepB = NF / (4 * Q);
    for (int w = tid; w < NF / 16; w += NT) {
        const int j = w & (Q - 1);
        const int c = w / Q;
        const int base = c * 16 * Q + j;
        float2 a[16];
#pragma unroll
        for (int r = 0; r < 16; r++) a[r] = B(buf, base + r * Q);
        // stage A (q = 4Q): butterflies over {r', r'+4, r'+8, r'+12}
#pragma unroll
        for (int rp = 0; rp < 4; rp++) {
            const int e = (j + rp * Q) * stepA;
            float2 w1 = gtw(tw, e);
            float2 w2 = cmul(w1, w1);
            float2 w3 = cmul(w2, w1);
            DIF_BFLY(a[rp], a[rp + 4], a[rp + 8], a[rp + 12], w1, w2, w3);
        }
        // stage B (q = Q): butterflies over {4s..4s+3}; twiddle independent of s
        {
            float2 w1 = gtw(tw, j * stepB);
            float2 w2 = cmul(w1, w1);
            float2 w3 = cmul(w2, w1);
#pragma unroll
            for (int s = 0; s < 4; s++)
                DIF_BFLY(a[4 * s], a[4 * s + 1], a[4 * s + 2], a[4 * s + 3], w1, w2, w3);
        }
#pragma unroll
        for (int r = 0; r < 16; r++) B(buf, base + r * Q) = a[r];
    }
}

// Fused inverse pass: DIT stages q = Q then q = 4Q, register-staged.
template <int Q>
__device__ __forceinline__ void inv_pass(float2* buf, const float2* tw, int tid) {
    const int stepS = NF / (4 * Q);
    const int stepL = NF / (16 * Q);
    for (int w = tid; w < NF / 16; w += NT) {
        const int j = w & (Q - 1);
        const int c = w / Q;
        const int base = c * 16 * Q + j;
        float2 a[16];
#pragma unroll
        for (int r = 0; r < 16; r++) a[r] = B(buf, base + r * Q);
        // stage small (q = Q): over {4s..4s+3}; twiddle independent of s
        {
            float2 w1 = gtwc(tw, j * stepS);
            float2 w2 = cmul(w1, w1);
            float2 w3 = cmul(w2, w1);
#pragma unroll
            for (int s = 0; s < 4; s++)
                DIT_BFLY(a[4 * s], a[4 * s + 1], a[4 * s + 2], a[4 * s + 3], w1, w2, w3);
        }
        // stage large (q = 4Q): over {r', r'+4, r'+8, r'+12}
#pragma unroll
        for (int rp = 0; rp < 4; rp++) {
            const int e = (j + rp * Q) * stepL;
            float2 w1 = gtwc(tw, e);
            float2 w2 = cmul(w1, w1);
            float2 w3 = cmul(w2, w1);
            DIT_BFLY(a[rp], a[rp + 4], a[rp + 8], a[rp + 12], w1, w2, w3);
        }
#pragma unroll
        for (int r = 0; r < 16; r++) B(buf, base + r * Q) = a[r];
    }
}

__global__ void __launch_bounds__(NT, 1)
fft_conv_kernel(const float* __restrict__ Xg, const float* __restrict__ Hg,
                float* __restrict__ Yg)
{
    extern __shared__ float2 smem[];
    float2* buf = smem;          // NFP padded complex work buffer
    float2* tw  = smem + NFP;    // NH twiddles exp(-2*pi*i*j/NF)

    const int tid = threadIdx.x;
    const size_t off = (size_t)blockIdx.x * NH;
    const float* x = Xg + off;
    const float* h = Hg + off;
    float* y = Yg + off;

    // twiddle table + load z = x + i*h (upper half implicit zero)
    for (int j = tid; j < NH; j += NT) {
        float s, c;
        sincospif((float)j * (-2.0f / (float)NF), &s, &c);
        tw[j] = make_float2(c, s);
        B(buf, j) = make_float2(x[j], h[j]);
    }
    __syncthreads();

    // ---- forward stage 0 (q = NF/4): a2 = a3 = 0 (zero padding)
    {
        const int q = NF / 4;
        for (int j = tid; j < q; j += NT) {
            float2 a0 = B(buf, j);
            float2 a1 = B(buf, j + q);
            float2 A0 = make_float2(a0.x + a1.x, a0.y + a1.y);
            float2 A1 = make_float2(a0.x + a1.y, a0.y - a1.x);   // a0 - i a1
            float2 A2 = make_float2(a0.x - a1.x, a0.y - a1.y);
            float2 A3 = make_float2(a0.x - a1.y, a0.y + a1.x);   // a0 + i a1
            float2 w1 = gtw(tw, j);
            float2 w2 = cmul(w1, w1);
            float2 w3 = cmul(w2, w1);
            B(buf, j)         = A0;
            B(buf, j +     q) = cmul(A1, w1);
            B(buf, j + 2 * q) = cmul(A2, w2);
            B(buf, j + 3 * q) = cmul(A3, w3);
        }
    }
    __syncthreads();

    fwd_pass<256>(buf, tw, tid);   // stages q=1024, q=256
    __syncthreads();
    fwd_pass<16>(buf, tw, tid);    // stages q=64, q=16
    __syncthreads();
    fwd_pass<1>(buf, tw, tid);     // stages q=4, q=1
    __syncthreads();

    // ---- pointwise: unpack X,H from packed Z, W = X*H (digit-reversed order)
    for (int p = tid; p < NF; p += NT) {
        const int k = drev14(p);
        if (k > NH) continue;
        if (k == 0 || k == NH) {
            float2 z = B(buf, p);
            B(buf, p) = make_float2(z.x * z.y, 0.0f);
        } else {
            const int p2 = drev14(NF - k);
            float2 zk = B(buf, p);
            float2 zm = B(buf, p2);
            float2 X = make_float2(0.5f * (zk.x + zm.x),  0.5f * (zk.y - zm.y));
            float2 H = make_float2(0.5f * (zk.y + zm.y), -0.5f * (zk.x - zm.x));
            float2 W = cmul(X, H);
            B(buf, p)  = W;
            B(buf, p2) = make_float2(W.x, -W.y);
        }
    }
    __syncthreads();

    inv_pass<1>(buf, tw, tid);     // stages q=1, q=4
    __syncthreads();
    inv_pass<16>(buf, tw, tid);    // stages q=16, q=64
    __syncthreads();
    inv_pass<256>(buf, tw, tid);   // stages q=256, q=1024
    __syncthreads();

    // ---- final inverse stage (q = NF/4) fused with output: only Re Y0, Re Y1
    {
        const int q = NF / 4;
        const float scale = 1.0f / ((float)NF * (float)NF);
        for (int j = tid; j < q; j += NT) {
            float2 w1 = gtwc(tw, j);
            float2 w2 = cmul(w1, w1);
            float2 w3 = cmul(w2, w1);
            float2 b0 = B(buf, j);
            float2 b1 = cmul(B(buf, j + q),     w1);
            float2 b2 = cmul(B(buf, j + 2 * q), w2);
            float2 b3 = cmul(B(buf, j + 3 * q), w3);
            y[j]     = (b0.x + b1.x + b2.x + b3.x) * scale;
            y[j + q] = ((b0.x - b2.x) - (b1.y - b3.y)) * scale;
        }
    }
}

extern "C" void kernel_launch(void* const* d_in, const int* in_sizes, int n_in,
                              void* d_out, int out_size) {
    const float* x = (const float*)d_in[0];
    const float* h = (const float*)d_in[1];
    float* y = (float*)d_out;
    const int rows = in_sizes[0] / NH;   // 4096

    cudaFuncSetAttribute(fft_conv_kernel,
                         cudaFuncAttributeMaxDynamicSharedMemorySize, SMEM_BYTES);
    fft_conv_kernel<<<rows, NT, SMEM_BYTES>>>(x, h, y);
}

// round 7
// speedup vs baseline: 1.1096x; 1.1096x over previous
#include <cuda_runtime.h>
#include <math.h>

// FFT long convolution: y = (x (*) h)[0:L] / (2L), per row.
// n = 16384 complex FFT per row, z = x + i*h packing. One CTA per row.
// Fused register-staged radix-16 passes (2x radix-4 in registers).
// Pads: buf index i -> i + (i>>5); twiddle index t -> t + (t>>5).
// Stage-A twiddles: one table load + constant 16th-root rotations.

#define NF 16384
#define NH 8192
#define NT 512
#define NFP (NF + (NF >> 5))                     // 16896 float2
#define TWP (NH + (NH >> 5))                     // 8448 float2
#define SMEM_BYTES ((NFP + TWP) * (int)sizeof(float2))  // 202752 B

__device__ __forceinline__ float2& B(float2* buf, int i) {
    return buf[i + (i >> 5)];
}
__device__ __forceinline__ float2& TW(float2* tw, int t) {
    return tw[t + (t >> 5)];
}

__device__ __forceinline__ float2 cmul(float2 a, float2 b) {
    return make_float2(a.x * b.x - a.y * b.y, a.x * b.y + a.y * b.x);
}

// twiddle: exp(-2*pi*i*e/NF); padded table holds e in [0, NH)
__device__ __forceinline__ float2 gtw(float2* tw, int e) {
    float2 t = TW(tw, e & (NH - 1));
    if (e & NH) { t.x = -t.x; t.y = -t.y; }
    return t;
}
__device__ __forceinline__ float2 gtwc(float2* tw, int e) {
    float2 t = gtw(tw, e);
    t.y = -t.y;
    return t;
}

// base-4 digit reversal of 7 digits (14 bits)
__device__ __forceinline__ int drev14(int p) {
    unsigned r = __brev((unsigned)p) >> 18;
    return (int)(((r & 0x1555u) << 1) | ((r >> 1) & 0x1555u));
}

// 16th roots: W^(rp*NF/16) = exp(-i*pi*rp/8), and conjugates
#define C16_C1 0.92387953251128674f   // cos(pi/8)
#define C16_S1 0.38268343236508978f   // sin(pi/8)
#define C16_C2 0.70710678118654752f   // cos(pi/4)

__device__ __forceinline__ float2 c16f(int rp) {   // forward
    switch (rp) {
        case 1:  return make_float2(C16_C1, -C16_S1);
        case 2:  return make_float2(C16_C2, -C16_C2);
        case 3:  return make_float2(C16_S1, -C16_C1);
        default: return make_float2(1.0f, 0.0f);
    }
}
__device__ __forceinline__ float2 c16i(int rp) {   // inverse (conjugate)
    switch (rp) {
        case 1:  return make_float2(C16_C1,  C16_S1);
        case 2:  return make_float2(C16_C2,  C16_C2);
        case 3:  return make_float2(C16_S1,  C16_C1);
        default: return make_float2(1.0f, 0.0f);
    }
}

// ---- DIF radix-4 butterfly; legs 1..3 post-twiddled
#define DIF_BFLY(a0, a1, a2, a3, w1, w2, w3)                                  \
    {                                                                          \
        float2 t0 = make_float2(a0.x + a2.x, a0.y + a2.y);                     \
        float2 t1 = make_float2(a0.x - a2.x, a0.y - a2.y);                     \
        float2 t2 = make_float2(a1.x + a3.x, a1.y + a3.y);                     \
        float2 t3 = make_float2(a1.x - a3.x, a1.y - a3.y);                     \
        float2 A0 = make_float2(t0.x + t2.x, t0.y + t2.y);                     \
        float2 A2 = make_float2(t0.x - t2.x, t0.y - t2.y);                     \
        float2 A1 = make_float2(t1.x + t3.y, t1.y - t3.x);  /* t1 - i t3 */    \
        float2 A3 = make_float2(t1.x - t3.y, t1.y + t3.x);  /* t1 + i t3 */    \
        a0 = A0; a1 = cmul(A1, w1); a2 = cmul(A2, w2); a3 = cmul(A3, w3);      \
    }

// ---- DIT radix-4 butterfly; legs 1..3 pre-twiddled
#define DIT_BFLY(a0, a1, a2, a3, w1, w2, w3)                                  \
    {                                                                          \
        float2 b0 = a0;                                                        \
        float2 b1 = cmul(a1, w1);                                              \
        float2 b2 = cmul(a2, w2);                                              \
        float2 b3 = cmul(a3, w3);                                              \
        float2 s0 = make_float2(b0.x + b2.x, b0.y + b2.y);                     \
        float2 s1 = make_float2(b0.x - b2.x, b0.y - b2.y);                     \
        float2 s2 = make_float2(b1.x + b3.x, b1.y + b3.y);                     \
        float2 s3 = make_float2(b1.x - b3.x, b1.y - b3.y);                     \
        a0 = make_float2(s0.x + s2.x, s0.y + s2.y);                            \
        a1 = make_float2(s1.x - s3.y, s1.y + s3.x);  /* s1 + i s3 */           \
        a2 = make_float2(s0.x - s2.x, s0.y - s2.y);                            \
        a3 = make_float2(s1.x + s3.y, s1.y - s3.x);  /* s1 - i s3 */           \
    }

// Fused forward pass: DIF stages q_A = 4Q then q_B = Q, register-staged.
template <int Q>
__device__ __forceinline__ void fwd_pass(float2* buf, float2* tw, int tid) {
    const int stepA = NF / (16 * Q);
    const int stepB = NF / (4 * Q);
    for (int w = tid; w < NF / 16; w += NT) {
        const int j = w & (Q - 1);
        const int c = w / Q;
        const int base = c * 16 * Q + j;
        float2 a[16];
#pragma unroll
        for (int r = 0; r < 16; r++) a[r] = B(buf, base + r * Q);
        // stage A (q=4Q): e = j*stepA + rp*NF/16 -> one LDS + constant rotations
        float2 wj = (Q == 1) ? make_float2(1.0f, 0.0f) : gtw(tw, j * stepA);
#pragma unroll
        for (int rp = 0; rp < 4; rp++) {
            float2 w1 = (rp == 0) ? wj : cmul(wj, c16f(rp));
            float2 w2 = cmul(w1, w1);
            float2 w3 = cmul(w2, w1);
            DIF_BFLY(a[rp], a[rp + 4], a[rp + 8], a[rp + 12], w1, w2, w3);
        }
        // stage B (q=Q): twiddle independent of s; identity when Q==1
        {
            float2 w1 = (Q == 1) ? make_float2(1.0f, 0.0f) : gtw(tw, j * stepB);
            float2 w2 = cmul(w1, w1);
            float2 w3 = cmul(w2, w1);
#pragma unroll
            for (int s = 0; s < 4; s++)
                DIF_BFLY(a[4 * s], a[4 * s + 1], a[4 * s + 2], a[4 * s + 3], w1, w2, w3);
        }
#pragma unroll
        for (int r = 0; r < 16; r++) B(buf, base + r * Q) = a[r];
    }
}

// Fused inverse pass: DIT stages q = Q then q = 4Q, register-staged.
template <int Q>
__device__ __forceinline__ void inv_pass(float2* buf, float2* tw, int tid) {
    const int stepS = NF / (4 * Q);
    const int stepL = NF / (16 * Q);
    for (int w = tid; w < NF / 16; w += NT) {
        const int j = w & (Q - 1);
        const int c = w / Q;
        const int base = c * 16 * Q + j;
        float2 a[16];
#pragma unroll
        for (int r = 0; r < 16; r++) a[r] = B(buf, base + r * Q);
        // stage small (q=Q): identity when Q==1
        {
            float2 w1 = (Q == 1) ? make_float2(1.0f, 0.0f) : gtwc(tw, j * stepS);
            float2 w2 = cmul(w1, w1);
            float2 w3 = cmul(w2, w1);
#pragma unroll
            for (int s = 0; s < 4; s++)
                DIT_BFLY(a[4 * s], a[4 * s + 1], a[4 * s + 2], a[4 * s + 3], w1, w2, w3);
        }
        // stage large (q=4Q): e = j*stepL + rp*NF/16
        float2 wj = (Q == 1) ? make_float2(1.0f, 0.0f) : gtwc(tw, j * stepL);
#pragma unroll
        for (int rp = 0; rp < 4; rp++) {
            float2 w1 = (rp == 0) ? wj : cmul(wj, c16i(rp));
            float2 w2 = cmul(w1, w1);
            float2 w3 = cmul(w2, w1);
            DIT_BFLY(a[rp], a[rp + 4], a[rp + 8], a[rp + 12], w1, w2, w3);
        }
#pragma unroll
        for (int r = 0; r < 16; r++) B(buf, base + r * Q) = a[r];
    }
}

__global__ void __launch_bounds__(NT, 1)
fft_conv_kernel(const float* __restrict__ Xg, const float* __restrict__ Hg,
                float* __restrict__ Yg)
{
    extern __shared__ float2 smem[];
    float2* buf = smem;          // NFP padded complex work buffer
    float2* tw  = smem + NFP;    // TWP padded twiddles exp(-2*pi*i*j/NF)

    const int tid = threadIdx.x;
    const size_t off = (size_t)blockIdx.x * NH;
    const float* x = Xg + off;
    const float* h = Hg + off;
    float* y = Yg + off;

    // twiddle table + load z = x + i*h (upper half implicit zero)
    for (int j = tid; j < NH; j += NT) {
        float s, c;
        sincospif((float)j * (-2.0f / (float)NF), &s, &c);
        TW(tw, j) = make_float2(c, s);
        B(buf, j) = make_float2(x[j], h[j]);
    }
    __syncthreads();

    // ---- forward stage 0 (q = NF/4): a2 = a3 = 0 (zero padding)
    {
        const int q = NF / 4;
        for (int j = tid; j < q; j += NT) {
            float2 a0 = B(buf, j);
            float2 a1 = B(buf, j + q);
            float2 A0 = make_float2(a0.x + a1.x, a0.y + a1.y);
            float2 A1 = make_float2(a0.x + a1.y, a0.y - a1.x);   // a0 - i a1
            float2 A2 = make_float2(a0.x - a1.x, a0.y - a1.y);
            float2 A3 = make_float2(a0.x - a1.y, a0.y + a1.x);   // a0 + i a1
            float2 w1 = gtw(tw, j);
            float2 w2 = cmul(w1, w1);
            float2 w3 = cmul(w2, w1);
            B(buf, j)         = A0;
            B(buf, j +     q) = cmul(A1, w1);
            B(buf, j + 2 * q) = cmul(A2, w2);
            B(buf, j + 3 * q) = cmul(A3, w3);
        }
    }
    __syncthreads();

    fwd_pass<256>(buf, tw, tid);   // stages q=1024, q=256
    __syncthreads();
    fwd_pass<16>(buf, tw, tid);    // stages q=64, q=16
    __syncthreads();
    fwd_pass<1>(buf, tw, tid);     // stages q=4, q=1 (constant twiddles)
    __syncthreads();

    // ---- pointwise: unpack X,H from packed Z, W = X*H (digit-reversed order)
    for (int p = tid; p < NF; p += NT) {
        const int k = drev14(p);
        if (k > NH) continue;
        if (k == 0 || k == NH) {
            float2 z = B(buf, p);
            B(buf, p) = make_float2(z.x * z.y, 0.0f);
        } else {
            const int p2 = drev14(NF - k);
            float2 zk = B(buf, p);
            float2 zm = B(buf, p2);
            float2 X = make_float2(0.5f * (zk.x + zm.x),  0.5f * (zk.y - zm.y));
            float2 H = make_float2(0.5f * (zk.y + zm.y), -0.5f * (zk.x - zm.x));
            float2 W = cmul(X, H);
            B(buf, p)  = W;
            B(buf, p2) = make_float2(W.x, -W.y);
        }
    }
    __syncthreads();

    inv_pass<1>(buf, tw, tid);     // stages q=1, q=4 (constant twiddles)
    __syncthreads();
    inv_pass<16>(buf, tw, tid);    // stages q=16, q=64
    __syncthreads();
    inv_pass<256>(buf, tw, tid);   // stages q=256, q=1024
    __syncthreads();

    // ---- final inverse stage (q = NF/4) fused with output: only Re Y0, Re Y1
    {
        const int q = NF / 4;
        const float scale = 1.0f / ((float)NF * (float)NF);
        for (int j = tid; j < q; j += NT) {
            float2 w1 = gtwc(tw, j);
            float2 w2 = cmul(w1, w1);
            float2 w3 = cmul(w2, w1);
            float2 b0 = B(buf, j);
            float2 b1 = cmul(B(buf, j + q),     w1);
            float2 b2 = cmul(B(buf, j + 2 * q), w2);
            float2 b3 = cmul(B(buf, j + 3 * q), w3);
            y[j]     = (b0.x + b1.x + b2.x + b3.x) * scale;
            y[j + q] = ((b0.x - b2.x) - (b1.y - b3.y)) * scale;
        }
    }
}

extern "C" void kernel_launch(void* const* d_in, const int* in_sizes, int n_in,
                              void* d_out, int out_size) {
    const float* x = (const float*)d_in[0];
    const float* h = (const float*)d_in[1];
    float* y = (float*)d_out;
    const int rows = in_sizes[0] / NH;   // 4096

    cudaFuncSetAttribute(fft_conv_kernel,
                         cudaFuncAttributeMaxDynamicSharedMemorySize, SMEM_BYTES);
    fft_conv_kernel<<<rows, NT, SMEM_BYTES>>>(x, h, y);
}